// round 14
// baseline (speedup 1.0000x reference)
#include <cuda_runtime.h>
#include <cuda_fp16.h>
#include <cstdint>

#define N_NODES 50000
#define N_EDGES 800000
#define D 64
#define NV4 (D/4)
#define NHQ 8                   // uint4 (8 halves) per fp16 row
#define CAP 64                  // bucket slots per node (max degree guard)

#define WPITCH 68               // padded row (floats) of transposed W in smem
#define PACK 33554432.0         // 2^25: count increment in packed double

// Scratch (device globals; zero-initialized at module load, re-zeroed at tail)
__device__ double g_degcnt[N_NODES];        // cnt*2^25 + sum(w)
__device__ float  g_dinv[N_NODES];
__device__ int    g_cnt [N_NODES];
__device__ int2   g_bkt [(size_t)N_NODES * CAP];   // {src, w bits}
__device__ uint4  g_hs  [N_NODES * NHQ];    // layer-1 fp16 features
__device__ uint4  g_hs2 [N_NODES * NHQ];    // layer-2 fp16 features

// ---------------------------------------------------------------------------
// Single-pass bucket fill: ONE atomic per edge (round-12 proven form).
// ---------------------------------------------------------------------------
__global__ void __launch_bounds__(256)
k_fill(const int* __restrict__ row, const int* __restrict__ col,
       const float* __restrict__ w) {
    int e = blockIdx.x * blockDim.x + threadIdx.x;
    if (e >= N_EDGES) return;
    int   c  = __ldg(&col[e]);
    float we = __ldg(&w[e]);
    double old = atomicAdd(&g_degcnt[c], (double)we + PACK);
    int slot = (int)(old * (1.0 / PACK));      // exact: frac part < 2^25
    if (slot < CAP)
        g_bkt[(size_t)c * CAP + slot] = make_int2(__ldg(&row[e]), __float_as_int(we));
}

// dinv + count extraction from packed degcnt
__global__ void k_dinv() {
    int i = blockIdx.x * blockDim.x + threadIdx.x;
    if (i >= N_NODES) return;
    double pk = g_degcnt[i];
    int cn = (int)(pk * (1.0 / PACK));
    float deg = (float)(pk - (double)cn * PACK);
    g_dinv[i] = rsqrtf(1.0f + deg);            // +1 = self-loop
    g_cnt[i] = (cn < CAP) ? cn : CAP;
}

// Tail cleanup (overlapped, off critical path)
__global__ void k_clean() {
    int i = blockIdx.x * blockDim.x + threadIdx.x;
    if (i < N_NODES) g_degcnt[i] = 0.0;
}

// ---------------------------------------------------------------------------
// GEMM (layer 1): hs[r] = fp16(in[r] @ W^T)
// One thread per output row; Wt broadcast LDS.128; packed fma.rn.f32x2.
// ---------------------------------------------------------------------------
__global__ void __launch_bounds__(128, 4)
k_gemm(const float* __restrict__ in, const float* __restrict__ W,
       uint4* __restrict__ hs) {
    __shared__ float Wt[D * WPITCH];       // Wt[k][c] = W[c][k]

    const int tid = threadIdx.x;
    for (int i = tid; i < D * D; i += 128) {
        int c = i >> 6, k = i & 63;
        Wt[k * WPITCH + c] = __ldg(&W[i]);
    }
    __syncthreads();

    const int r = blockIdx.x * 128 + tid;
    if (r >= N_NODES) return;

    const float4* xr = (const float4*)(in + (size_t)r * D);

    unsigned long long acc[32];
    #pragma unroll
    for (int j = 0; j < 32; ++j) acc[j] = 0ULL;

    float4 xa = __ldg(&xr[0]);
    #pragma unroll 2
    for (int kb = 0; kb < 16; ++kb) {
        float4 xn = xa;
        if (kb < 15) xn = __ldg(&xr[kb + 1]);
        const float xs[4] = {xa.x, xa.y, xa.z, xa.w};
        #pragma unroll
        for (int kk = 0; kk < 4; ++kk) {
            const int k = kb * 4 + kk;
            unsigned long long xx;
            asm("mov.b64 %0, {%1, %1};" : "=l"(xx) : "r"(__float_as_uint(xs[kk])));
            const float4* wrow = (const float4*)&Wt[k * WPITCH];
            #pragma unroll
            for (int j = 0; j < 16; ++j) {
                float4 w4 = wrow[j];
                unsigned long long w01, w23;
                asm("mov.b64 %0, {%1, %2};" : "=l"(w01) : "f"(w4.x), "f"(w4.y));
                asm("mov.b64 %0, {%1, %2};" : "=l"(w23) : "f"(w4.z), "f"(w4.w));
                asm("fma.rn.f32x2 %0, %1, %2, %0;" : "+l"(acc[2*j])     : "l"(xx), "l"(w01));
                asm("fma.rn.f32x2 %0, %1, %2, %0;" : "+l"(acc[2*j + 1]) : "l"(xx), "l"(w23));
            }
        }
        xa = xn;
    }

    uint4* o = &hs[(size_t)r * NHQ];
    #pragma unroll
    for (int jj = 0; jj < 8; ++jj) {
        float f[8];
        #pragma unroll
        for (int m = 0; m < 4; ++m) {
            asm("mov.b64 {%0, %1}, %2;" : "=f"(f[2*m]), "=f"(f[2*m+1]) : "l"(acc[4*jj + m]));
        }
        __half2 h0 = __floats2half2_rn(f[0], f[1]);
        __half2 h1 = __floats2half2_rn(f[2], f[3]);
        __half2 h2 = __floats2half2_rn(f[4], f[5]);
        __half2 h3 = __floats2half2_rn(f[6], f[7]);
        uint4 vv;
        vv.x = *(unsigned*)&h0; vv.y = *(unsigned*)&h1;
        vv.z = *(unsigned*)&h2; vv.w = *(unsigned*)&h3;
        o[jj] = vv;
    }
}

// ---------------------------------------------------------------------------
// Shared agg helper: 8 threads/node, thread q owns dims 8q..8q+7
// ---------------------------------------------------------------------------
__device__ __forceinline__ void acc_edge(float* acc, float w, uint4 hv) {
    float2 f0 = __half22float2(*(__half2*)&hv.x);
    float2 f1 = __half22float2(*(__half2*)&hv.y);
    float2 f2 = __half22float2(*(__half2*)&hv.z);
    float2 f3 = __half22float2(*(__half2*)&hv.w);
    acc[0] = fmaf(w, f0.x, acc[0]); acc[1] = fmaf(w, f0.y, acc[1]);
    acc[2] = fmaf(w, f1.x, acc[2]); acc[3] = fmaf(w, f1.y, acc[3]);
    acc[4] = fmaf(w, f2.x, acc[4]); acc[5] = fmaf(w, f2.y, acc[5]);
    acc[6] = fmaf(w, f3.x, acc[6]); acc[7] = fmaf(w, f3.y, acc[7]);
}

__device__ __forceinline__ void agg_node(const uint4* __restrict__ hs,
                                         int n, int q, float di, float* acc) {
    {
        uint4 sv = __ldg(&hs[(size_t)n * NHQ + q]);
        float2 f0 = __half22float2(*(__half2*)&sv.x);
        float2 f1 = __half22float2(*(__half2*)&sv.y);
        float2 f2 = __half22float2(*(__half2*)&sv.z);
        float2 f3 = __half22float2(*(__half2*)&sv.w);
        acc[0] = di * f0.x; acc[1] = di * f0.y;
        acc[2] = di * f1.x; acc[3] = di * f1.y;
        acc[4] = di * f2.x; acc[5] = di * f2.y;
        acc[6] = di * f3.x; acc[7] = di * f3.y;
    }
    const int2* bkt = &g_bkt[(size_t)n * CAP];
    const int cn = __ldg(&g_cnt[n]);
    int i = 0;
    for (; i + 3 < cn; i += 4) {
        int2 e0 = __ldg(&bkt[i]);
        int2 e1 = __ldg(&bkt[i + 1]);
        int2 e2 = __ldg(&bkt[i + 2]);
        int2 e3 = __ldg(&bkt[i + 3]);
        float d0 = __ldg(&g_dinv[e0.x]);
        float d1 = __ldg(&g_dinv[e1.x]);
        float d2 = __ldg(&g_dinv[e2.x]);
        float d3 = __ldg(&g_dinv[e3.x]);
        uint4 h0 = __ldg(&hs[(size_t)e0.x * NHQ + q]);
        uint4 h1 = __ldg(&hs[(size_t)e1.x * NHQ + q]);
        uint4 h2 = __ldg(&hs[(size_t)e2.x * NHQ + q]);
        uint4 h3 = __ldg(&hs[(size_t)e3.x * NHQ + q]);
        acc_edge(acc, __int_as_float(e0.y) * d0, h0);
        acc_edge(acc, __int_as_float(e1.y) * d1, h1);
        acc_edge(acc, __int_as_float(e2.y) * d2, h2);
        acc_edge(acc, __int_as_float(e3.y) * d3, h3);
    }
    for (; i < cn; ++i) {
        int2 e0 = __ldg(&bkt[i]);
        float d0 = __ldg(&g_dinv[e0.x]);
        uint4 h0 = __ldg(&hs[(size_t)e0.x * NHQ + q]);
        acc_edge(acc, __int_as_float(e0.y) * d0, h0);
    }
}

// ---------------------------------------------------------------------------
// FUSED agg1 + epilogue(b1, relu) + GEMM(W2): hs2[n] = fp16(x1[n] @ W2^T)
// 8 threads/node; x1 row staged in smem; one __syncthreads.
// ---------------------------------------------------------------------------
__global__ void __launch_bounds__(256)
k_agg_gemm(const uint4* __restrict__ hs, const float* __restrict__ b1,
           const float* __restrict__ W2, uint4* __restrict__ hs2) {
    __shared__ float Wt[D * WPITCH];       // Wt[k][c] = W2[c][k]
    __shared__ float x1s[32 * D];          // 32 nodes per block

    const int tid = threadIdx.x;
    for (int i = tid; i < D * D; i += 256) {
        int c = i >> 6, k = i & 63;
        Wt[k * WPITCH + c] = __ldg(&W2[i]);
    }

    const int gtid = blockIdx.x * 256 + tid;
    int n = gtid >> 3;
    const int q = gtid & 7;
    const bool valid = (n < N_NODES);
    if (!valid) n = N_NODES - 1;           // clamp; no early return (syncthreads below)

    const float di = g_dinv[n];
    float acc[8];
    agg_node(hs, n, q, di, acc);

    // epilogue -> stage x1 row slice in smem
    const int nl = tid >> 3;               // node-local 0..31
    float* xrow = &x1s[nl * D + q * 8];
    #pragma unroll
    for (int j = 0; j < 8; ++j)
        xrow[j] = fmaxf(fmaf(di, acc[j], __ldg(&b1[q * 8 + j])), 0.f);

    __syncthreads();                       // covers Wt writes + x1s writes

    // gemm: thread computes output dims [8q, 8q+8) for its node
    unsigned long long h2[4];
    #pragma unroll
    for (int m = 0; m < 4; ++m) h2[m] = 0ULL;
    const float* xs = &x1s[nl * D];
    #pragma unroll 4
    for (int k = 0; k < D; ++k) {
        float xk = xs[k];                  // broadcast within node group
        unsigned long long xx;
        asm("mov.b64 %0, {%1, %1};" : "=l"(xx) : "r"(__float_as_uint(xk)));
        const float4* wr = (const float4*)&Wt[k * WPITCH + q * 8];
        float4 w0 = wr[0];
        float4 w1 = wr[1];
        unsigned long long wa, wb, wc, wd;
        asm("mov.b64 %0, {%1, %2};" : "=l"(wa) : "f"(w0.x), "f"(w0.y));
        asm("mov.b64 %0, {%1, %2};" : "=l"(wb) : "f"(w0.z), "f"(w0.w));
        asm("mov.b64 %0, {%1, %2};" : "=l"(wc) : "f"(w1.x), "f"(w1.y));
        asm("mov.b64 %0, {%1, %2};" : "=l"(wd) : "f"(w1.z), "f"(w1.w));
        asm("fma.rn.f32x2 %0, %1, %2, %0;" : "+l"(h2[0]) : "l"(xx), "l"(wa));
        asm("fma.rn.f32x2 %0, %1, %2, %0;" : "+l"(h2[1]) : "l"(xx), "l"(wb));
        asm("fma.rn.f32x2 %0, %1, %2, %0;" : "+l"(h2[2]) : "l"(xx), "l"(wc));
        asm("fma.rn.f32x2 %0, %1, %2, %0;" : "+l"(h2[3]) : "l"(xx), "l"(wd));
    }

    if (valid) {
        float f[8];
        #pragma unroll
        for (int m = 0; m < 4; ++m)
            asm("mov.b64 {%0, %1}, %2;" : "=f"(f[2*m]), "=f"(f[2*m+1]) : "l"(h2[m]));
        __half2 p0 = __floats2half2_rn(f[0], f[1]);
        __half2 p1 = __floats2half2_rn(f[2], f[3]);
        __half2 p2 = __floats2half2_rn(f[4], f[5]);
        __half2 p3 = __floats2half2_rn(f[6], f[7]);
        uint4 vv;
        vv.x = *(unsigned*)&p0; vv.y = *(unsigned*)&p1;
        vv.z = *(unsigned*)&p2; vv.w = *(unsigned*)&p3;
        hs2[(size_t)n * NHQ + q] = vv;
    }
}

// ---------------------------------------------------------------------------
// Final aggregation (layer 2): out = dinv*acc + b2  (no relu)
// ---------------------------------------------------------------------------
__global__ void __launch_bounds__(256)
k_agg(const uint4* __restrict__ hs, const float* __restrict__ b,
      float4* __restrict__ out) {
    const int tid = blockIdx.x * blockDim.x + threadIdx.x;
    const int n = tid >> 3;
    if (n >= N_NODES) return;
    const int q = tid & 7;

    const float di = g_dinv[n];
    float acc[8];
    agg_node(hs, n, q, di, acc);

    const float4* bv = (const float4*)b;
    float4 b0 = __ldg(&bv[q * 2]);
    float4 b1 = __ldg(&bv[q * 2 + 1]);
    float4 o0, o1;
    o0.x = fmaf(di, acc[0], b0.x); o0.y = fmaf(di, acc[1], b0.y);
    o0.z = fmaf(di, acc[2], b0.z); o0.w = fmaf(di, acc[3], b0.w);
    o1.x = fmaf(di, acc[4], b1.x); o1.y = fmaf(di, acc[5], b1.y);
    o1.z = fmaf(di, acc[6], b1.z); o1.w = fmaf(di, acc[7], b1.w);
    out[n * NV4 + q * 2]     = o0;
    out[n * NV4 + q * 2 + 1] = o1;
}

// ---------------------------------------------------------------------------
// Launch: gemm1 ∥ prep; fused agg1+gemm2; agg2; clean overlapped.
// ---------------------------------------------------------------------------
extern "C" void kernel_launch(void* const* d_in, const int* in_sizes, int n_in,
                              void* d_out, int out_size) {
    const float* x  = (const float*)d_in[0];
    const float* ew = (const float*)d_in[1];
    const float* W1 = (const float*)d_in[2];
    const float* b1 = (const float*)d_in[3];
    const float* W2 = (const float*)d_in[4];
    const float* b2 = (const float*)d_in[5];
    const int*   ei = (const int*)  d_in[6];
    const int* row = ei;            // edge_index[0] = sources
    const int* col = ei + N_EDGES;  // edge_index[1] = targets
    float* out = (float*)d_out;

    void* p;
    cudaGetSymbolAddress(&p, g_hs);   uint4* hs  = (uint4*)p;
    cudaGetSymbolAddress(&p, g_hs2);  uint4* hs2 = (uint4*)p;

    static cudaStream_t s2 = nullptr;
    static cudaEvent_t ev_fork = nullptr, ev_gemm1 = nullptr, ev_prep = nullptr, ev_clean = nullptr;
    if (!s2) {
        cudaStreamCreateWithFlags(&s2, cudaStreamNonBlocking);
        cudaEventCreateWithFlags(&ev_fork, cudaEventDisableTiming);
        cudaEventCreateWithFlags(&ev_gemm1, cudaEventDisableTiming);
        cudaEventCreateWithFlags(&ev_prep, cudaEventDisableTiming);
        cudaEventCreateWithFlags(&ev_clean, cudaEventDisableTiming);
    }

    const int TB = 256;
    int gemm_grid = (N_NODES + 127) / 128;
    int node_grid = (N_NODES + TB - 1) / TB;
    int edge_grid = (N_EDGES + TB - 1) / TB;
    int agg_grid  = (N_NODES * 8 + TB - 1) / TB;

    // Fork: layer-1 GEMM on side stream (independent of dinv / buckets)
    cudaEventRecord(ev_fork, 0);
    cudaStreamWaitEvent(s2, ev_fork, 0);
    k_gemm<<<gemm_grid, 128, 0, s2>>>(x, W1, hs);
    cudaEventRecord(ev_gemm1, s2);

    // Prep chain on main stream
    k_fill<<<edge_grid, TB>>>(row, col, ew);
    k_dinv<<<node_grid, TB>>>();
    cudaEventRecord(ev_prep, 0);

    // Cleanup on side stream after degcnt consumed (overlaps fused agg)
    cudaStreamWaitEvent(s2, ev_prep, 0);
    k_clean<<<node_grid, TB, 0, s2>>>();
    cudaEventRecord(ev_clean, s2);

    // Join, then fused layer-1 agg + layer-2 gemm, then final agg
    cudaStreamWaitEvent(0, ev_gemm1, 0);
    k_agg_gemm<<<agg_grid, TB>>>((const uint4*)hs, b1, W2, hs2);
    k_agg<<<agg_grid, TB>>>((const uint4*)hs2, b2, (float4*)out);
    cudaStreamWaitEvent(0, ev_clean, 0);
}

// round 17
// speedup vs baseline: 1.1598x; 1.1598x over previous
#include <cuda_runtime.h>
#include <cuda_fp16.h>
#include <cstdint>

#define N_NODES 50000
#define N_EDGES 800000
#define D 64
#define NV4 (D/4)
#define NHQ 8                   // uint4 (8 halves) per fp16 row
#define CAP 64                  // bucket slots per node (max degree guard)

#define WPITCH 68               // padded row (floats) of transposed W in smem
#define PACK 33554432.0         // 2^25: count increment in packed double

// Scratch (device globals; zero-initialized at module load, re-zeroed at tail)
__device__ double g_degcnt[N_NODES];        // cnt*2^25 + sum(w)
__device__ float  g_dinv[N_NODES];
__device__ int    g_cnt [N_NODES];
__device__ int2   g_bkt [(size_t)N_NODES * CAP];   // {src, w bits}
__device__ uint4  g_hs  [N_NODES * NHQ];    // fp16 features, 8 halves per uint4
__device__ float  g_x1  [N_NODES * D];

// ---------------------------------------------------------------------------
// Single-pass bucket fill: ONE atomic per edge.
// Return value of the packed-double atomic gives the slot index AND
// accumulates the weighted degree.
// ---------------------------------------------------------------------------
__global__ void __launch_bounds__(256)
k_fill(const int* __restrict__ row, const int* __restrict__ col,
       const float* __restrict__ w) {
    int e = blockIdx.x * blockDim.x + threadIdx.x;
    if (e >= N_EDGES) return;
    int   c  = __ldg(&col[e]);
    float we = __ldg(&w[e]);
    double old = atomicAdd(&g_degcnt[c], (double)we + PACK);
    int slot = (int)(old * (1.0 / PACK));      // exact: frac part < 2^25
    if (slot < CAP)
        g_bkt[(size_t)c * CAP + slot] = make_int2(__ldg(&row[e]), __float_as_int(we));
}

// dinv + count extraction from packed degcnt
__global__ void k_dinv() {
    int i = blockIdx.x * blockDim.x + threadIdx.x;
    if (i >= N_NODES) return;
    double pk = g_degcnt[i];
    int cn = (int)(pk * (1.0 / PACK));
    float deg = (float)(pk - (double)cn * PACK);
    g_dinv[i] = rsqrtf(1.0f + deg);            // +1 = self-loop
    g_cnt[i] = (cn < CAP) ? cn : CAP;
}

// Tail cleanup: restore invariant launch-entry state (overlapped, off critical path)
__global__ void k_clean() {
    int i = blockIdx.x * blockDim.x + threadIdx.x;
    if (i < N_NODES) g_degcnt[i] = 0.0;
}

// ---------------------------------------------------------------------------
// GEMM: hs[r] = fp16(in[r] @ W^T)
// One thread per output row; Wt broadcast LDS.128; packed fma.rn.f32x2.
// ---------------------------------------------------------------------------
__global__ void __launch_bounds__(128, 4)
k_gemm(const float* __restrict__ in, const float* __restrict__ W,
       uint4* __restrict__ hs) {
    __shared__ float Wt[D * WPITCH];       // Wt[k][c] = W[c][k]

    const int tid = threadIdx.x;
    for (int i = tid; i < D * D; i += 128) {
        int c = i >> 6, k = i & 63;
        Wt[k * WPITCH + c] = __ldg(&W[i]);
    }
    __syncthreads();

    const int r = blockIdx.x * 128 + tid;
    if (r >= N_NODES) return;

    const float4* xr = (const float4*)(in + (size_t)r * D);

    unsigned long long acc[32];            // acc[k] = dims {2k, 2k+1}
    #pragma unroll
    for (int j = 0; j < 32; ++j) acc[j] = 0ULL;

    float4 xa = __ldg(&xr[0]);
    #pragma unroll 2
    for (int kb = 0; kb < 16; ++kb) {
        float4 xn = xa;
        if (kb < 15) xn = __ldg(&xr[kb + 1]);      // one-ahead prefetch
        const float xs[4] = {xa.x, xa.y, xa.z, xa.w};
        #pragma unroll
        for (int kk = 0; kk < 4; ++kk) {
            const int k = kb * 4 + kk;
            unsigned long long xx;
            asm("mov.b64 %0, {%1, %1};" : "=l"(xx) : "r"(__float_as_uint(xs[kk])));
            const float4* wrow = (const float4*)&Wt[k * WPITCH];
            #pragma unroll
            for (int j = 0; j < 16; ++j) {
                float4 w4 = wrow[j];               // broadcast LDS.128
                unsigned long long w01, w23;
                asm("mov.b64 %0, {%1, %2};" : "=l"(w01) : "f"(w4.x), "f"(w4.y));
                asm("mov.b64 %0, {%1, %2};" : "=l"(w23) : "f"(w4.z), "f"(w4.w));
                asm("fma.rn.f32x2 %0, %1, %2, %0;" : "+l"(acc[2*j])     : "l"(xx), "l"(w01));
                asm("fma.rn.f32x2 %0, %1, %2, %0;" : "+l"(acc[2*j + 1]) : "l"(xx), "l"(w23));
            }
        }
        xa = xn;
    }

    // Pack to fp16 and store: 8 x STG.128
    uint4* o = &hs[(size_t)r * NHQ];
    #pragma unroll
    for (int jj = 0; jj < 8; ++jj) {
        float f[8];
        #pragma unroll
        for (int m = 0; m < 4; ++m) {
            asm("mov.b64 {%0, %1}, %2;" : "=f"(f[2*m]), "=f"(f[2*m+1]) : "l"(acc[4*jj + m]));
        }
        __half2 h0 = __floats2half2_rn(f[0], f[1]);
        __half2 h1 = __floats2half2_rn(f[2], f[3]);
        __half2 h2 = __floats2half2_rn(f[4], f[5]);
        __half2 h3 = __floats2half2_rn(f[6], f[7]);
        uint4 vv;
        vv.x = *(unsigned*)&h0; vv.y = *(unsigned*)&h1;
        vv.z = *(unsigned*)&h2; vv.w = *(unsigned*)&h3;
        o[jj] = vv;
    }
}

// ---------------------------------------------------------------------------
// Bucket aggregation + epilogue. 4 threads per node, thread q owns dims 16q..16q+15.
//   acc = dinv[n]*hs[n] + sum_e (w_e * dinv[src_e]) * hs[src_e]
//   out[n] = (relu?) dinv[n]*acc + b
// Per edge per thread: 2 independent LDG.128; 4-edge unroll => 8 gathers in flight.
// Shared (bkt/dinv/w*d) work amortized over only 4 threads.
// ---------------------------------------------------------------------------
__device__ __forceinline__ void acc8(float* a, float w, uint4 hv) {
    float2 f0 = __half22float2(*(__half2*)&hv.x);
    float2 f1 = __half22float2(*(__half2*)&hv.y);
    float2 f2 = __half22float2(*(__half2*)&hv.z);
    float2 f3 = __half22float2(*(__half2*)&hv.w);
    a[0] = fmaf(w, f0.x, a[0]); a[1] = fmaf(w, f0.y, a[1]);
    a[2] = fmaf(w, f1.x, a[2]); a[3] = fmaf(w, f1.y, a[3]);
    a[4] = fmaf(w, f2.x, a[4]); a[5] = fmaf(w, f2.y, a[5]);
    a[6] = fmaf(w, f3.x, a[6]); a[7] = fmaf(w, f3.y, a[7]);
}

__global__ void __launch_bounds__(256)
k_agg(const uint4* __restrict__ hs, const float* __restrict__ b,
      float4* __restrict__ out, int relu) {
    const int tid = blockIdx.x * blockDim.x + threadIdx.x;
    const int n = tid >> 2;
    if (n >= N_NODES) return;
    const int q = tid & 3;                 // owns uint4 slots {2q, 2q+1}

    const float di = g_dinv[n];
    float acc[16];
    {
        uint4 s0 = __ldg(&hs[(size_t)n * NHQ + 2*q]);
        uint4 s1 = __ldg(&hs[(size_t)n * NHQ + 2*q + 1]);
        float2 t;
        t = __half22float2(*(__half2*)&s0.x); acc[0] = di*t.x; acc[1] = di*t.y;
        t = __half22float2(*(__half2*)&s0.y); acc[2] = di*t.x; acc[3] = di*t.y;
        t = __half22float2(*(__half2*)&s0.z); acc[4] = di*t.x; acc[5] = di*t.y;
        t = __half22float2(*(__half2*)&s0.w); acc[6] = di*t.x; acc[7] = di*t.y;
        t = __half22float2(*(__half2*)&s1.x); acc[8] = di*t.x; acc[9] = di*t.y;
        t = __half22float2(*(__half2*)&s1.y); acc[10]= di*t.x; acc[11]= di*t.y;
        t = __half22float2(*(__half2*)&s1.z); acc[12]= di*t.x; acc[13]= di*t.y;
        t = __half22float2(*(__half2*)&s1.w); acc[14]= di*t.x; acc[15]= di*t.y;
    }

    const int2* bkt = &g_bkt[(size_t)n * CAP];
    const int cn = __ldg(&g_cnt[n]);

    int i = 0;
    for (; i + 3 < cn; i += 4) {
        int2 e0 = __ldg(&bkt[i]);
        int2 e1 = __ldg(&bkt[i + 1]);
        int2 e2 = __ldg(&bkt[i + 2]);
        int2 e3 = __ldg(&bkt[i + 3]);
        float w0 = __int_as_float(e0.y) * __ldg(&g_dinv[e0.x]);
        float w1 = __int_as_float(e1.y) * __ldg(&g_dinv[e1.x]);
        float w2 = __int_as_float(e2.y) * __ldg(&g_dinv[e2.x]);
        float w3 = __int_as_float(e3.y) * __ldg(&g_dinv[e3.x]);
        uint4 a0 = __ldg(&hs[(size_t)e0.x * NHQ + 2*q]);
        uint4 c0 = __ldg(&hs[(size_t)e0.x * NHQ + 2*q + 1]);
        uint4 a1 = __ldg(&hs[(size_t)e1.x * NHQ + 2*q]);
        uint4 c1 = __ldg(&hs[(size_t)e1.x * NHQ + 2*q + 1]);
        uint4 a2 = __ldg(&hs[(size_t)e2.x * NHQ + 2*q]);
        uint4 c2 = __ldg(&hs[(size_t)e2.x * NHQ + 2*q + 1]);
        uint4 a3 = __ldg(&hs[(size_t)e3.x * NHQ + 2*q]);
        uint4 c3 = __ldg(&hs[(size_t)e3.x * NHQ + 2*q + 1]);
        acc8(acc,     w0, a0); acc8(acc + 8, w0, c0);
        acc8(acc,     w1, a1); acc8(acc + 8, w1, c1);
        acc8(acc,     w2, a2); acc8(acc + 8, w2, c2);
        acc8(acc,     w3, a3); acc8(acc + 8, w3, c3);
    }
    for (; i < cn; ++i) {
        int2 e0 = __ldg(&bkt[i]);
        float w0 = __int_as_float(e0.y) * __ldg(&g_dinv[e0.x]);
        uint4 a0 = __ldg(&hs[(size_t)e0.x * NHQ + 2*q]);
        uint4 c0 = __ldg(&hs[(size_t)e0.x * NHQ + 2*q + 1]);
        acc8(acc, w0, a0); acc8(acc + 8, w0, c0);
    }

    const float4* bv = (const float4*)b;
    #pragma unroll
    for (int h = 0; h < 4; ++h) {
        float4 bb = __ldg(&bv[q * 4 + h]);
        float4 o;
        o.x = fmaf(di, acc[4*h + 0], bb.x);
        o.y = fmaf(di, acc[4*h + 1], bb.y);
        o.z = fmaf(di, acc[4*h + 2], bb.z);
        o.w = fmaf(di, acc[4*h + 3], bb.w);
        if (relu) {
            o.x = fmaxf(o.x, 0.f); o.y = fmaxf(o.y, 0.f);
            o.z = fmaxf(o.z, 0.f); o.w = fmaxf(o.w, 0.f);
        }
        out[n * NV4 + q * 4 + h] = o;
    }
}

// ---------------------------------------------------------------------------
// Launch: fork layer-1 GEMM onto side stream; cleanup overlapped at tail.
// ---------------------------------------------------------------------------
extern "C" void kernel_launch(void* const* d_in, const int* in_sizes, int n_in,
                              void* d_out, int out_size) {
    const float* x  = (const float*)d_in[0];
    const float* ew = (const float*)d_in[1];
    const float* W1 = (const float*)d_in[2];
    const float* b1 = (const float*)d_in[3];
    const float* W2 = (const float*)d_in[4];
    const float* b2 = (const float*)d_in[5];
    const int*   ei = (const int*)  d_in[6];
    const int* row = ei;            // edge_index[0] = sources
    const int* col = ei + N_EDGES;  // edge_index[1] = targets
    float* out = (float*)d_out;

    void* p;
    cudaGetSymbolAddress(&p, g_hs);   uint4* hs = (uint4*)p;
    cudaGetSymbolAddress(&p, g_x1);   float* x1 = (float*)p;

    static cudaStream_t s2 = nullptr;
    static cudaEvent_t ev_fork = nullptr, ev_gemm1 = nullptr, ev_prep = nullptr, ev_clean = nullptr;
    if (!s2) {
        cudaStreamCreateWithFlags(&s2, cudaStreamNonBlocking);
        cudaEventCreateWithFlags(&ev_fork, cudaEventDisableTiming);
        cudaEventCreateWithFlags(&ev_gemm1, cudaEventDisableTiming);
        cudaEventCreateWithFlags(&ev_prep, cudaEventDisableTiming);
        cudaEventCreateWithFlags(&ev_clean, cudaEventDisableTiming);
    }

    const int TB = 256;
    int gemm_grid = (N_NODES + 127) / 128;
    int node_grid = (N_NODES + TB - 1) / TB;
    int edge_grid = (N_EDGES + TB - 1) / TB;
    int agg_grid  = (N_NODES * 4 + TB - 1) / TB;

    // Fork: layer-1 GEMM on side stream (independent of dinv / buckets)
    cudaEventRecord(ev_fork, 0);
    cudaStreamWaitEvent(s2, ev_fork, 0);
    k_gemm<<<gemm_grid, 128, 0, s2>>>(x, W1, hs);
    cudaEventRecord(ev_gemm1, s2);

    // Prep chain on main stream: one atomic pass + tiny node pass
    k_fill<<<edge_grid, TB>>>(row, col, ew);
    k_dinv<<<node_grid, TB>>>();
    cudaEventRecord(ev_prep, 0);

    // Cleanup on side stream after degcnt consumed (overlaps agg1)
    cudaStreamWaitEvent(s2, ev_prep, 0);
    k_clean<<<node_grid, TB, 0, s2>>>();
    cudaEventRecord(ev_clean, s2);

    // Join, then layer-1 agg, layer-2
    cudaStreamWaitEvent(0, ev_gemm1, 0);
    k_agg<<<agg_grid, TB>>>((const uint4*)hs, b1, (float4*)x1, 1);
    k_gemm<<<gemm_grid, 128>>>(x1, W2, hs);
    k_agg<<<agg_grid, TB>>>((const uint4*)hs, b2, (float4*)out, 0);
    cudaStreamWaitEvent(0, ev_clean, 0);
}